// round 2
// baseline (speedup 1.0000x reference)
#include <cuda_runtime.h>
#include <math_constants.h>

// EvenLayer min-sum check-node update — float4 vectorized.
//
// Structure (proved in R0, rel_err = 0.0): the lexsort permutation in the
// reference mask builder is the identity, so check(e) = e % 600 and the
// neighbor set of edge e is { (e%600) + 600*m : m=0..5 } \ {e}.
//
// This round: 4 checks per thread via float4 (all 16B-aligned), 2D grid
// (5 blocks x 8 batches) x 32 threads. Per thread: 6 LDG.128 (x) +
// 6 LDG.128 (bias) front-batched (MLP=12), then pure register math,
// then 6 STG.128. Kernel is launch/latency-floor bound; this minimizes
// the issued-instruction tail and exposed DRAM latency.

#define N_CHK 600
#define BATCH 8
#define E     3600
#define DEG   6
#define Q     (N_CHK / 4)   // 150 float4-groups of checks per batch

__global__ __launch_bounds__(32)
void even_layer_kernel(const float* __restrict__ x,
                       const float* __restrict__ bias,
                       float* __restrict__ out)
{
    const int t = blockIdx.x * 32 + threadIdx.x;   // float4-group id, 0..159
    if (t >= Q) return;
    const int b = blockIdx.y;

    const float4* __restrict__ x4 = (const float4*)(x + b * E);
    const float4* __restrict__ b4 = (const float4*)bias;
    float4* __restrict__ o4       = (float4*)(out + b * E);

    // Front-batch all independent loads (12 x LDG.128 in flight).
    float4 v[DEG], bs[DEG];
#pragma unroll
    for (int m = 0; m < DEG; ++m) v[m]  = x4[m * Q + t];
#pragma unroll
    for (int m = 0; m < DEG; ++m) bs[m] = b4[m * Q + t];

    float4 o[DEG];

#pragma unroll
    for (int j = 0; j < 4; ++j) {              // 4 checks in this float4 group
        float w[DEG];
#pragma unroll
        for (int m = 0; m < DEG; ++m)
            w[m] = ((const float*)&v[m])[j];

#pragma unroll
        for (int i = 0; i < DEG; ++i) {        // exclusive reduce per edge
            float p  = 1.0f;
            float mn = CUDART_INF_F;
#pragma unroll
            for (int k = 0; k < DEG; ++k) {
                if (k != i) {
                    p  = p * w[k];
                    mn = fminf(mn, fabsf(w[k]));
                }
            }
            // sign() incl. sign(0)=0, matching jnp.sign(prod(...))
            const float s = (p > 0.0f) ? 1.0f : ((p < 0.0f) ? -1.0f : 0.0f);
            const float r = fmaxf(mn - ((const float*)&bs[i])[j], 0.0f);
            ((float*)&o[i])[j] = s * r;
        }
    }

#pragma unroll
    for (int m = 0; m < DEG; ++m)
        o4[m * Q + t] = o[m];
}

extern "C" void kernel_launch(void* const* d_in, const int* in_sizes, int n_in,
                              void* d_out, int out_size)
{
    // metadata order: inputs [BATCH,E] f32, bias [1,E] f32, inf_mask [E,E] f32 (unused)
    const float* x    = (const float*)d_in[0];
    const float* bias = (const float*)d_in[1];
    float* out        = (float*)d_out;

    dim3 grid((Q + 31) / 32, BATCH);   // (5, 8) = 40 single-warp blocks
    even_layer_kernel<<<grid, 32>>>(x, bias, out);
}

// round 3
// speedup vs baseline: 1.4444x; 1.4444x over previous
#include <cuda_runtime.h>
#include <math_constants.h>

// EvenLayer min-sum check-node update — scalar per-check (R1 shape), with
// 2D grid (no integer division on the address path) and explicitly
// front-batched loads (MLP=12/thread).
//
// Structure (proved in R0, rel_err = 0.0): the lexsort permutation in the
// reference mask builder is the identity, so check(e) = e % 600 and the
// neighbor set of edge e is { (e%600) + 600*m : m=0..5 } \ {e}.

#define N_CHK 600
#define BATCH 8
#define E     3600
#define DEG   6

__global__ __launch_bounds__(128)
void even_layer_kernel(const float* __restrict__ x,
                       const float* __restrict__ bias,
                       float* __restrict__ out)
{
    const int c = blockIdx.x * 128 + threadIdx.x;   // check id, 0..639
    if (c >= N_CHK) return;
    const int b = blockIdx.y;                        // batch id

    const float* __restrict__ xb = x + b * E + c;
    const float* __restrict__ bb = bias + c;
    float* __restrict__ ob       = out + b * E + c;

    // Front-batch ALL independent loads: 12 LDGs in flight, one exposed
    // DRAM round trip total.
    float v[DEG], bs[DEG];
#pragma unroll
    for (int m = 0; m < DEG; ++m) v[m]  = xb[m * N_CHK];
#pragma unroll
    for (int m = 0; m < DEG; ++m) bs[m] = bb[m * N_CHK];

#pragma unroll
    for (int i = 0; i < DEG; ++i) {        // exclusive reduce per edge
        float p  = 1.0f;
        float mn = CUDART_INF_F;
#pragma unroll
        for (int k = 0; k < DEG; ++k) {
            if (k != i) {
                p  = p * v[k];
                mn = fminf(mn, fabsf(v[k]));
            }
        }
        // sign() incl. sign(0)=0, matching jnp.sign(prod(...)); keep the
        // actual fp32 product (bit-XOR sign would diverge on underflow).
        const float s = (p > 0.0f) ? 1.0f : ((p < 0.0f) ? -1.0f : 0.0f);
        ob[i * N_CHK] = s * fmaxf(mn - bs[i], 0.0f);
    }
}

extern "C" void kernel_launch(void* const* d_in, const int* in_sizes, int n_in,
                              void* d_out, int out_size)
{
    // metadata order: inputs [BATCH,E] f32, bias [1,E] f32, inf_mask [E,E] f32 (unused)
    const float* x    = (const float*)d_in[0];
    const float* bias = (const float*)d_in[1];
    float* out        = (float*)d_out;

    dim3 grid((N_CHK + 127) / 128, BATCH);   // (5, 8) = 40 blocks x 4 warps
    even_layer_kernel<<<grid, 128>>>(x, bias, out);
}